// round 1
// baseline (speedup 1.0000x reference)
#include <cuda_runtime.h>
#include <cuda_bf16.h>
#include <math.h>

// Problem constants (DeBERTa layer)
#define BATCH 16
#define SEQ   512
#define HID   1024
#define NHEAD 8
#define HDIM  128
#define FFDIM 3072
#define MTOT  (BATCH * SEQ)        // 8192 rows

// ---------------- scratch (device globals; no allocation allowed) ----------
__device__ float g_h[(size_t)MTOT * HID];      // embeddings after LN / later reused for pre-LN2
__device__ float g_q[(size_t)MTOT * HID];      // q, later ctx
__device__ float g_k[(size_t)MTOT * HID];      // k, later pre-LN1 tmp
__device__ float g_v[(size_t)MTOT * HID];      // v, later attn_out
__device__ float g_s[(size_t)BATCH * NHEAD * SEQ * SEQ];  // scores / probs (in place)
__device__ float g_ff[(size_t)MTOT * FFDIM];   // gelu(ffn intermediate)

// ---------------- reductions ----------------
__device__ __forceinline__ float warpSum(float v) {
#pragma unroll
    for (int o = 16; o > 0; o >>= 1) v += __shfl_xor_sync(0xffffffffu, v, o);
    return v;
}
__device__ __forceinline__ float warpMax(float v) {
#pragma unroll
    for (int o = 16; o > 0; o >>= 1) v = fmaxf(v, __shfl_xor_sync(0xffffffffu, v, o));
    return v;
}

// LayerNorm over one row of 1024 floats. 256 threads, each holds one float4.
// v: this thread's 4 input values. Writes normalized output to outrow.
__device__ __forceinline__ void ln_store(float4 v, const float* __restrict__ g,
                                         const float* __restrict__ b,
                                         float* __restrict__ outrow, int t) {
    __shared__ float red[8];
    __shared__ float stat[2];
    float s = v.x + v.y + v.z + v.w;
    s = warpSum(s);
    if ((t & 31) == 0) red[t >> 5] = s;
    __syncthreads();
    if (t < 32) {
        float x = (t < 8) ? red[t] : 0.0f;
        x = warpSum(x);
        if (t == 0) stat[0] = x * (1.0f / (float)HID);
    }
    __syncthreads();
    float m = stat[0];
    float dx = v.x - m, dy = v.y - m, dz = v.z - m, dw = v.w - m;
    float s2 = dx * dx + dy * dy + dz * dz + dw * dw;
    s2 = warpSum(s2);
    if ((t & 31) == 0) red[t >> 5] = s2;
    __syncthreads();
    if (t < 32) {
        float x = (t < 8) ? red[t] : 0.0f;
        x = warpSum(x);
        if (t == 0) stat[1] = rsqrtf(x * (1.0f / (float)HID) + 1e-7f);
    }
    __syncthreads();
    float r = stat[1];
    float4 gv = ((const float4*)g)[t];
    float4 bv = ((const float4*)b)[t];
    float4 o;
    o.x = dx * r * gv.x + bv.x;
    o.y = dy * r * gv.y + bv.y;
    o.z = dz * r * gv.z + bv.z;
    o.w = dw * r * gv.w + bv.w;
    ((float4*)outrow)[t] = o;
}

// ---------------- GEMM core: 128x128x16 tiles, 256 threads, 8x8 microtile --
// EPI: 0=plain, 1=+bias, 2=+bias+residual, 3=gelu(x+bias), 4=x*scale
template <int EPI, bool TRANSB>
__device__ __forceinline__ void gemm_body(
    const float* __restrict__ A, int lda,
    const float* __restrict__ Bm, int ldb,
    float* __restrict__ C, int ldc, int K,
    const float* __restrict__ bias, const float* __restrict__ res, float scale) {
    __shared__ float As[16][132];
    __shared__ float Bs[16][132];
    float acc[8][8];
#pragma unroll
    for (int i = 0; i < 8; i++)
#pragma unroll
        for (int j = 0; j < 8; j++) acc[i][j] = 0.0f;

    const int tid = threadIdx.x;
    const int tileM = blockIdx.y * 128;
    const int tileN = blockIdx.x * 128;
    const int arow = tid >> 2;
    const int acol = (tid & 3) << 2;
    const int brow = TRANSB ? (tid >> 2) : (tid >> 5);
    const int bcol = TRANSB ? ((tid & 3) << 2) : ((tid & 31) << 2);
    const int tr = (tid >> 4) << 3;
    const int tc = (tid & 15) << 3;

    for (int k0 = 0; k0 < K; k0 += 16) {
        float4 a0 = *(const float4*)(A + (size_t)(tileM + arow) * lda + (k0 + acol));
        float4 a1 = *(const float4*)(A + (size_t)(tileM + arow + 64) * lda + (k0 + acol));
        float4 b0, b1;
        if (TRANSB) {
            b0 = *(const float4*)(Bm + (size_t)(tileN + brow) * ldb + (k0 + bcol));
            b1 = *(const float4*)(Bm + (size_t)(tileN + brow + 64) * ldb + (k0 + bcol));
        } else {
            b0 = *(const float4*)(Bm + (size_t)(k0 + brow) * ldb + (tileN + bcol));
            b1 = *(const float4*)(Bm + (size_t)(k0 + brow + 8) * ldb + (tileN + bcol));
        }
        As[acol + 0][arow] = a0.x; As[acol + 1][arow] = a0.y;
        As[acol + 2][arow] = a0.z; As[acol + 3][arow] = a0.w;
        As[acol + 0][arow + 64] = a1.x; As[acol + 1][arow + 64] = a1.y;
        As[acol + 2][arow + 64] = a1.z; As[acol + 3][arow + 64] = a1.w;
        if (TRANSB) {
            Bs[bcol + 0][brow] = b0.x; Bs[bcol + 1][brow] = b0.y;
            Bs[bcol + 2][brow] = b0.z; Bs[bcol + 3][brow] = b0.w;
            Bs[bcol + 0][brow + 64] = b1.x; Bs[bcol + 1][brow + 64] = b1.y;
            Bs[bcol + 2][brow + 64] = b1.z; Bs[bcol + 3][brow + 64] = b1.w;
        } else {
            *(float4*)&Bs[brow][bcol] = b0;
            *(float4*)&Bs[brow + 8][bcol] = b1;
        }
        __syncthreads();
#pragma unroll
        for (int kk = 0; kk < 16; kk++) {
            float a[8], bb[8];
            *(float4*)(a) = *(const float4*)&As[kk][tr];
            *(float4*)(a + 4) = *(const float4*)&As[kk][tr + 4];
            *(float4*)(bb) = *(const float4*)&Bs[kk][tc];
            *(float4*)(bb + 4) = *(const float4*)&Bs[kk][tc + 4];
#pragma unroll
            for (int i = 0; i < 8; i++)
#pragma unroll
                for (int j = 0; j < 8; j++) acc[i][j] = fmaf(a[i], bb[j], acc[i][j]);
        }
        __syncthreads();
    }

#pragma unroll
    for (int i = 0; i < 8; i++) {
        const int m = tileM + tr + i;
#pragma unroll
        for (int jb = 0; jb < 2; jb++) {
            const int n = tileN + tc + jb * 4;
            float4 o;
            float* op = &o.x;
#pragma unroll
            for (int jj = 0; jj < 4; jj++) {
                float vv = acc[i][jb * 4 + jj];
                if (EPI == 4) vv *= scale;
                if (EPI >= 1 && EPI <= 3) vv += bias[n + jj];
                if (EPI == 2) vv += res[(size_t)m * ldc + n + jj];
                if (EPI == 3) vv = 0.5f * vv * (1.0f + erff(vv * 0.70710678118654752f));
                op[jj] = vv;
            }
            *(float4*)(C + (size_t)m * ldc + n) = o;
        }
    }
}

// ---------------- stage kernels ----------------
__global__ void __launch_bounds__(256) k_embed(const float* __restrict__ x,
                                               const float* __restrict__ pos,
                                               const float* __restrict__ g,
                                               const float* __restrict__ b) {
    int row = blockIdx.x;
    int s = row & (SEQ - 1);
    int t = threadIdx.x;
    float4 xv = ((const float4*)(x + (size_t)row * HID))[t];
    float4 pv = ((const float4*)(pos + (size_t)s * HID))[t];
    xv.x += pv.x; xv.y += pv.y; xv.z += pv.z; xv.w += pv.w;
    ln_store(xv, g, b, g_h + (size_t)row * HID, t);
}

__global__ void __launch_bounds__(256) k_gemm_q(const float* __restrict__ W,
                                                const float* __restrict__ bias) {
    gemm_body<1, false>(g_h, HID, W, HID, g_q, HID, HID, bias, nullptr, 0.0f);
}
__global__ void __launch_bounds__(256) k_gemm_k(const float* __restrict__ W) {
    gemm_body<0, false>(g_h, HID, W, HID, g_k, HID, HID, nullptr, nullptr, 0.0f);
}
__global__ void __launch_bounds__(256) k_gemm_v(const float* __restrict__ W,
                                                const float* __restrict__ bias) {
    gemm_body<1, false>(g_h, HID, W, HID, g_v, HID, HID, bias, nullptr, 0.0f);
}

// scores[bh] = (q/sqrt(HD)) @ k^T  for each (b,h); 512x512, K=128
__global__ void __launch_bounds__(256) k_scores() {
    int bh = blockIdx.z;
    int b = bh >> 3, hh = bh & 7;
    size_t off = (size_t)b * SEQ * HID + (size_t)hh * HDIM;
    gemm_body<4, true>(g_q + off, HID, g_k + off, HID,
                       g_s + (size_t)bh * SEQ * SEQ, SEQ, HDIM,
                       nullptr, nullptr, 0.08838834764831843f);
}

__global__ void __launch_bounds__(128) k_softmax() {
    __shared__ float red[4];
    __shared__ float stat0, stat1;
    size_t row = blockIdx.x;
    float* p = g_s + row * SEQ;
    int t = threadIdx.x;
    float4 v = ((float4*)p)[t];
    float mx = fmaxf(fmaxf(v.x, v.y), fmaxf(v.z, v.w));
    mx = warpMax(mx);
    if ((t & 31) == 0) red[t >> 5] = mx;
    __syncthreads();
    if (t < 32) {
        float x = (t < 4) ? red[t] : -3.4e38f;
        x = warpMax(x);
        if (t == 0) stat0 = x;
    }
    __syncthreads();
    mx = stat0;
    v.x = expf(v.x - mx); v.y = expf(v.y - mx);
    v.z = expf(v.z - mx); v.w = expf(v.w - mx);
    float s = v.x + v.y + v.z + v.w;
    s = warpSum(s);
    if ((t & 31) == 0) red[t >> 5] = s;
    __syncthreads();
    if (t < 32) {
        float x = (t < 4) ? red[t] : 0.0f;
        x = warpSum(x);
        if (t == 0) stat1 = 1.0f / x;
    }
    __syncthreads();
    float inv = stat1;
    v.x *= inv; v.y *= inv; v.z *= inv; v.w *= inv;
    ((float4*)p)[t] = v;
}

// ctx[bh] = probs[bh] @ v[bh]; 512x128, K=512. Writes into g_q (q is dead).
__global__ void __launch_bounds__(256) k_ctx() {
    int bh = blockIdx.z;
    int b = bh >> 3, hh = bh & 7;
    size_t off = (size_t)b * SEQ * HID + (size_t)hh * HDIM;
    gemm_body<0, false>(g_s + (size_t)bh * SEQ * SEQ, SEQ, g_v + off, HID,
                        g_q + off, HID, SEQ, nullptr, nullptr, 0.0f);
}

// pre-LN1 = ctx @ Wo + bo + h  -> g_k
__global__ void __launch_bounds__(256) k_gemm_o(const float* __restrict__ W,
                                                const float* __restrict__ bias) {
    gemm_body<2, false>(g_q, HID, W, HID, g_k, HID, HID, bias, g_h, 0.0f);
}

__global__ void __launch_bounds__(256) k_ln1(const float* __restrict__ g,
                                             const float* __restrict__ b) {
    int row = blockIdx.x;
    int t = threadIdx.x;
    float4 v = ((const float4*)(g_k + (size_t)row * HID))[t];
    ln_store(v, g, b, g_v + (size_t)row * HID, t);  // attn_out -> g_v
}

// ff = gelu(attn_out @ Wi + bi) -> g_ff
__global__ void __launch_bounds__(256) k_gemm_ff(const float* __restrict__ W,
                                                 const float* __restrict__ bias) {
    gemm_body<3, false>(g_v, HID, W, FFDIM, g_ff, FFDIM, HID, bias, nullptr, 0.0f);
}

// pre-LN2 = ff @ Wf + bf + attn_out -> g_h
__global__ void __launch_bounds__(256) k_gemm_f(const float* __restrict__ W,
                                                const float* __restrict__ bias) {
    gemm_body<2, false>(g_ff, FFDIM, W, HID, g_h, HID, FFDIM, bias, g_v, 0.0f);
}

__global__ void __launch_bounds__(256) k_ln2(const float* __restrict__ g,
                                             const float* __restrict__ b,
                                             float* __restrict__ out) {
    int row = blockIdx.x;
    int t = threadIdx.x;
    float4 v = ((const float4*)(g_h + (size_t)row * HID))[t];
    ln_store(v, g, b, out + (size_t)row * HID, t);
}

// ---------------- launch ----------------
extern "C" void kernel_launch(void* const* d_in, const int* in_sizes, int n_in,
                              void* d_out, int out_size) {
    const float* x        = (const float*)d_in[0];
    const float* pos_emb  = (const float*)d_in[1];
    const float* emb_ln_g = (const float*)d_in[2];
    const float* emb_ln_b = (const float*)d_in[3];
    const float* Wq       = (const float*)d_in[4];
    const float* Wk       = (const float*)d_in[5];
    const float* Wv       = (const float*)d_in[6];
    const float* q_bias   = (const float*)d_in[7];
    const float* v_bias   = (const float*)d_in[8];
    const float* Wo       = (const float*)d_in[9];
    const float* bo       = (const float*)d_in[10];
    const float* ln1_g    = (const float*)d_in[11];
    const float* ln1_b    = (const float*)d_in[12];
    const float* Wi       = (const float*)d_in[13];
    const float* bi       = (const float*)d_in[14];
    const float* Wf       = (const float*)d_in[15];
    const float* bf       = (const float*)d_in[16];
    const float* ln2_g    = (const float*)d_in[17];
    const float* ln2_b    = (const float*)d_in[18];
    float* out = (float*)d_out;

    dim3 gProj(HID / 128, MTOT / 128);        // (8, 64)
    dim3 gFF(FFDIM / 128, MTOT / 128);        // (24, 64)
    dim3 gScores(SEQ / 128, SEQ / 128, BATCH * NHEAD);  // (4,4,128)
    dim3 gCtx(HDIM / 128, SEQ / 128, BATCH * NHEAD);    // (1,4,128)

    k_embed<<<MTOT, 256>>>(x, pos_emb, emb_ln_g, emb_ln_b);
    k_gemm_q<<<gProj, 256>>>(Wq, q_bias);
    k_gemm_k<<<gProj, 256>>>(Wk);
    k_gemm_v<<<gProj, 256>>>(Wv, v_bias);
    k_scores<<<gScores, 256>>>();
    k_softmax<<<BATCH * NHEAD * SEQ, 128>>>();
    k_ctx<<<gCtx, 256>>>();
    k_gemm_o<<<gProj, 256>>>(Wo, bo);
    k_ln1<<<MTOT, 256>>>(ln1_g, ln1_b);
    k_gemm_ff<<<gFF, 256>>>(Wi, bi);
    k_gemm_f<<<gProj, 256>>>(Wf, bf);
    k_ln2<<<MTOT, 256>>>(ln2_g, ln2_b, out);
}

// round 3
// speedup vs baseline: 4.3613x; 4.3613x over previous
#include <cuda_runtime.h>
#include <cuda_fp16.h>
#include <math.h>
#include <stdint.h>

// Problem constants (DeBERTa layer)
#define BATCH 16
#define SEQ   512
#define HID   1024
#define NHEAD 8
#define HDIM  128
#define FFDIM 3072
#define MTOT  (BATCH * SEQ)        // 8192 rows
#define NBH   (BATCH * NHEAD)      // 128 (b,h) planes

// ---------------- scratch (device globals; no allocation allowed) ----------
__device__ __align__(16) float  g_h[(size_t)MTOT * HID];        // fp32 residual stream
__device__ __align__(16) float  g_attn32[(size_t)MTOT * HID];   // fp32 attn_out (residual for FF2)
__device__ __align__(16) float  g_s[(size_t)NBH * SEQ * SEQ];   // fp32 scores
__device__ __align__(16) __half g_h16[(size_t)MTOT * HID];
__device__ __align__(16) __half g_q16[(size_t)MTOT * HID];
__device__ __align__(16) __half g_k16[(size_t)MTOT * HID];
__device__ __align__(16) __half g_v16[(size_t)MTOT * HID];
__device__ __align__(16) __half g_vt[(size_t)NBH * HDIM * SEQ]; // V^T per (b,h): [128][512]
__device__ __align__(16) __half g_p[(size_t)NBH * SEQ * SEQ];   // fp16 probs
__device__ __align__(16) __half g_ctx16[(size_t)MTOT * HID];
__device__ __align__(16) __half g_attn16[(size_t)MTOT * HID];
__device__ __align__(16) __half g_ff16[(size_t)MTOT * FFDIM];
// fp16 transposed weights: [N, K] K-major
__device__ __align__(16) __half g_Wqt[(size_t)HID * HID];
__device__ __align__(16) __half g_Wkt[(size_t)HID * HID];
__device__ __align__(16) __half g_Wvt[(size_t)HID * HID];
__device__ __align__(16) __half g_Wot[(size_t)HID * HID];
__device__ __align__(16) __half g_Wit[(size_t)FFDIM * HID];
__device__ __align__(16) __half g_Wft[(size_t)HID * FFDIM];

// ---------------- low-level helpers (base sm_103 features only) -----------
__device__ __forceinline__ uint32_t smem_u32(const void* p) {
    uint32_t a;
    asm("{ .reg .u64 t; cvta.to.shared.u64 t, %1; cvt.u32.u64 %0, t; }" : "=r"(a) : "l"(p));
    return a;
}
__device__ __forceinline__ void cpasync16(uint32_t dst, const void* src) {
    asm volatile("cp.async.cg.shared.global [%0], [%1], 16;" :: "r"(dst), "l"(src));
}
__device__ __forceinline__ void cp_commit() {
    asm volatile("cp.async.commit_group;" ::: "memory");
}
__device__ __forceinline__ void cp_wait0() {
    asm volatile("cp.async.wait_group 0;" ::: "memory");
}
__device__ __forceinline__ void cp_wait1() {
    asm volatile("cp.async.wait_group 1;" ::: "memory");
}
__device__ __forceinline__ void ldsm4(uint32_t* a, uint32_t addr) {
    asm volatile("ldmatrix.sync.aligned.m8n8.x4.shared.b16 {%0,%1,%2,%3}, [%4];"
                 : "=r"(a[0]), "=r"(a[1]), "=r"(a[2]), "=r"(a[3]) : "r"(addr));
}
__device__ __forceinline__ void ldsm2(uint32_t* b, uint32_t addr) {
    asm volatile("ldmatrix.sync.aligned.m8n8.x2.shared.b16 {%0,%1}, [%2];"
                 : "=r"(b[0]), "=r"(b[1]) : "r"(addr));
}
__device__ __forceinline__ void mma16816(float* c, const uint32_t* a, const uint32_t* b) {
    asm volatile(
        "mma.sync.aligned.m16n8k16.row.col.f32.f16.f16.f32 "
        "{%0,%1,%2,%3}, {%4,%5,%6,%7}, {%8,%9}, {%0,%1,%2,%3};"
        : "+f"(c[0]), "+f"(c[1]), "+f"(c[2]), "+f"(c[3])
        : "r"(a[0]), "r"(a[1]), "r"(a[2]), "r"(a[3]), "r"(b[0]), "r"(b[1]));
}

// ---------------- mma.sync GEMM: 128x128 tile, BK=32, 256 threads ----------
// C[m][n] = sum_k A[m][k] * B[n][k]; A,B fp16 K-major; pointers pre-offset to tile.
// Epilogue: optional scale, bias, residual (fp32), exact GELU; out fp16 or fp32.
#define LDH 40  // smem row stride in halves (80B): conflict-free for ldmatrix

template <int HASBIAS, int HASRES, int GELU, int OUT16, int SCALED>
__device__ __forceinline__ void tc_gemm(
    const __half* __restrict__ A, int lda,
    const __half* __restrict__ B, int ldb,
    void* __restrict__ Cv, int ldc, int K,
    const float* __restrict__ bias, const float* __restrict__ res, float scale) {
    __shared__ __align__(16) __half sA[2][128 * LDH];
    __shared__ __align__(16) __half sB[2][128 * LDH];

    const int tid = threadIdx.x;
    const int lane = tid & 31;
    const int w = tid >> 5;
    const int wm = (w >> 2) * 64;   // warp M origin (2 rows of warps)
    const int wn = (w & 3) * 32;    // warp N origin (4 cols of warps)

    float acc[4][4][4];
#pragma unroll
    for (int i = 0; i < 4; i++)
#pragma unroll
        for (int j = 0; j < 4; j++)
#pragma unroll
            for (int e = 0; e < 4; e++) acc[i][j][e] = 0.0f;

    const uint32_t sA0 = smem_u32(sA);
    const uint32_t sB0 = smem_u32(sB);

    // global->smem mapping: thread covers row tid>>1, halves [(tid&1)*16, +16)
    const int lrow = tid >> 1;
    const int lcol = (tid & 1) * 16;
    const uint32_t dOffA = (uint32_t)(lrow * LDH + lcol) * 2;

    const int nch = K >> 5;
    // ldmatrix lane addressing
    const int r8 = lane & 7;
    const int q = lane >> 3;           // 0..3
    const int aRowOff = (q & 1) * 8 + r8;
    const int aColOff = (q >> 1) * 8;
    const int bRowOff = r8;
    const int bColOff = (q & 1) * 8;

#define LOAD_STAGE(s, k0)                                                          \
    {                                                                              \
        const __half* Ar = A + (size_t)lrow * lda + (k0) + lcol;                   \
        uint32_t da = sA0 + (s) * 128 * LDH * 2 + dOffA;                           \
        cpasync16(da, Ar); cpasync16(da + 16, Ar + 8);                             \
        const __half* Br = B + (size_t)lrow * ldb + (k0) + lcol;                   \
        uint32_t db = sB0 + (s) * 128 * LDH * 2 + dOffA;                           \
        cpasync16(db, Br); cpasync16(db + 16, Br + 8);                             \
        cp_commit();                                                               \
    }

    LOAD_STAGE(0, 0);
    for (int c = 0; c < nch; c++) {
        const int s = c & 1;
        if (c + 1 < nch) LOAD_STAGE((c + 1) & 1, (c + 1) * 32);
        if (c + 1 < nch) cp_wait1(); else cp_wait0();
        __syncthreads();

        const uint32_t baseA = sA0 + s * 128 * LDH * 2;
        const uint32_t baseB = sB0 + s * 128 * LDH * 2;
#pragma unroll
        for (int kk = 0; kk < 32; kk += 16) {
            uint32_t a[4][4], b[4][2];
#pragma unroll
            for (int i = 0; i < 4; i++)
                ldsm4(a[i], baseA + (uint32_t)((wm + i * 16 + aRowOff) * LDH + kk + aColOff) * 2);
#pragma unroll
            for (int j = 0; j < 4; j++)
                ldsm2(b[j], baseB + (uint32_t)((wn + j * 8 + bRowOff) * LDH + kk + bColOff) * 2);
#pragma unroll
            for (int i = 0; i < 4; i++)
#pragma unroll
                for (int j = 0; j < 4; j++) mma16816(acc[i][j], a[i], b[j]);
        }
        __syncthreads();
    }

    // epilogue
    const int gr = lane >> 2;         // 0..7
    const int gc = (lane & 3) * 2;    // 0,2,4,6
    float* Cf = (float*)Cv;
    __half* Ch = (__half*)Cv;
#pragma unroll
    for (int i = 0; i < 4; i++) {
#pragma unroll
        for (int j = 0; j < 4; j++) {
            const int col = wn + j * 8 + gc;
            float bx = 0.f, by = 0.f;
            if (HASBIAS) { bx = bias[col]; by = bias[col + 1]; }
#pragma unroll
            for (int half_ = 0; half_ < 2; half_++) {
                const int row = wm + i * 16 + gr + half_ * 8;
                float v0 = acc[i][j][half_ * 2 + 0];
                float v1 = acc[i][j][half_ * 2 + 1];
                if (SCALED) { v0 *= scale; v1 *= scale; }
                if (HASBIAS) { v0 += bx; v1 += by; }
                if (HASRES) {
                    const float* rp = res + (size_t)row * ldc + col;
                    v0 += rp[0]; v1 += rp[1];
                }
                if (GELU) {
                    v0 = 0.5f * v0 * (1.0f + erff(v0 * 0.70710678118654752f));
                    v1 = 0.5f * v1 * (1.0f + erff(v1 * 0.70710678118654752f));
                }
                if (OUT16) {
                    __half2 h = __floats2half2_rn(v0, v1);
                    *(__half2*)(Ch + (size_t)row * ldc + col) = h;
                } else {
                    float2 f = make_float2(v0, v1);
                    *(float2*)(Cf + (size_t)row * ldc + col) = f;
                }
            }
        }
    }
#undef LOAD_STAGE
}

// ---------------- GEMM wrapper kernels ----------------
__global__ void __launch_bounds__(256) k_proj_q(const float* __restrict__ bias) {
    int tM = blockIdx.y * 128, tN = blockIdx.x * 128;
    tc_gemm<1, 0, 0, 1, 0>(g_h16 + (size_t)tM * HID, HID, g_Wqt + (size_t)tN * HID, HID,
                           g_q16 + (size_t)tM * HID + tN, HID, HID, bias + tN, nullptr, 0.f);
}
__global__ void __launch_bounds__(256) k_proj_k() {
    int tM = blockIdx.y * 128, tN = blockIdx.x * 128;
    tc_gemm<0, 0, 0, 1, 0>(g_h16 + (size_t)tM * HID, HID, g_Wkt + (size_t)tN * HID, HID,
                           g_k16 + (size_t)tM * HID + tN, HID, HID, nullptr, nullptr, 0.f);
}
__global__ void __launch_bounds__(256) k_proj_v(const float* __restrict__ bias) {
    int tM = blockIdx.y * 128, tN = blockIdx.x * 128;
    tc_gemm<1, 0, 0, 1, 0>(g_h16 + (size_t)tM * HID, HID, g_Wvt + (size_t)tN * HID, HID,
                           g_v16 + (size_t)tM * HID + tN, HID, HID, bias + tN, nullptr, 0.f);
}
__global__ void __launch_bounds__(256) k_scores() {
    int bh = blockIdx.z;
    int b = bh >> 3, h = bh & 7;
    size_t off = (size_t)b * SEQ * HID + (size_t)h * HDIM;
    int tM = blockIdx.y * 128, tN = blockIdx.x * 128;
    tc_gemm<0, 0, 0, 0, 1>(g_q16 + off + (size_t)tM * HID, HID,
                           g_k16 + off + (size_t)tN * HID, HID,
                           g_s + (size_t)bh * SEQ * SEQ + (size_t)tM * SEQ + tN, SEQ, HDIM,
                           nullptr, nullptr, 0.08838834764831843f);
}
__global__ void __launch_bounds__(256) k_ctx() {
    int bh = blockIdx.z;
    int b = bh >> 3, h = bh & 7;
    int tM = blockIdx.y * 128;
    tc_gemm<0, 0, 0, 1, 0>(g_p + (size_t)bh * SEQ * SEQ + (size_t)tM * SEQ, SEQ,
                           g_vt + (size_t)bh * HDIM * SEQ, SEQ,
                           g_ctx16 + (size_t)b * SEQ * HID + (size_t)h * HDIM + (size_t)tM * HID,
                           HID, SEQ, nullptr, nullptr, 0.f);
}
__global__ void __launch_bounds__(256) k_proj_o(const float* __restrict__ bias) {
    int tM = blockIdx.y * 128, tN = blockIdx.x * 128;
    tc_gemm<1, 1, 0, 0, 0>(g_ctx16 + (size_t)tM * HID, HID, g_Wot + (size_t)tN * HID, HID,
                           g_h + (size_t)tM * HID + tN, HID, HID, bias + tN,
                           g_h + (size_t)tM * HID + tN, 0.f);
}
__global__ void __launch_bounds__(256) k_ff1(const float* __restrict__ bias) {
    int tM = blockIdx.y * 128, tN = blockIdx.x * 128;
    tc_gemm<1, 0, 1, 1, 0>(g_attn16 + (size_t)tM * HID, HID, g_Wit + (size_t)tN * HID, HID,
                           g_ff16 + (size_t)tM * FFDIM + tN, FFDIM, HID, bias + tN, nullptr, 0.f);
}
__global__ void __launch_bounds__(256) k_ff2(const float* __restrict__ bias) {
    int tM = blockIdx.y * 128, tN = blockIdx.x * 128;
    tc_gemm<1, 1, 0, 0, 0>(g_ff16 + (size_t)tM * FFDIM, FFDIM, g_Wft + (size_t)tN * FFDIM, FFDIM,
                           g_h + (size_t)tM * HID + tN, HID, FFDIM, bias + tN,
                           g_attn32 + (size_t)tM * HID + tN, 0.f);
}

// ---------------- weight transpose + fp32->fp16 convert: W[K,N] -> Wt[N,K] ----
__global__ void __launch_bounds__(256) k_wt(const float* __restrict__ W, __half* __restrict__ Wt,
                                            int K, int N) {
    __shared__ float t[32][33];
    int nb = blockIdx.x * 32, kb = blockIdx.y * 32;
    int tx = threadIdx.x & 31, ty = threadIdx.x >> 5;  // (32,8)
#pragma unroll
    for (int j = 0; j < 4; j++)
        t[ty + 8 * j][tx] = W[(size_t)(kb + ty + 8 * j) * N + nb + tx];
    __syncthreads();
#pragma unroll
    for (int j = 0; j < 4; j++)
        Wt[(size_t)(nb + ty + 8 * j) * K + kb + tx] = __float2half(t[tx][ty + 8 * j]);
}

// ---------------- v16 [B,S,H] -> vt [bh][HD][S] ----------------
__global__ void __launch_bounds__(256) k_vtrans() {
    __shared__ __half t[32][33];
    int bh = blockIdx.z;
    int b = bh >> 3, h = bh & 7;
    int sb = blockIdx.x * 32, db = blockIdx.y * 32;
    int tx = threadIdx.x & 31, ty = threadIdx.x >> 5;
#pragma unroll
    for (int j = 0; j < 4; j++)
        t[ty + 8 * j][tx] = g_v16[(size_t)(b * SEQ + sb + ty + 8 * j) * HID + h * HDIM + db + tx];
    __syncthreads();
#pragma unroll
    for (int j = 0; j < 4; j++)
        g_vt[(size_t)(bh * HDIM + db + ty + 8 * j) * SEQ + sb + tx] = t[tx][ty + 8 * j];
}

// ---------------- reductions / LN / softmax ----------------
__device__ __forceinline__ float warpSum(float v) {
#pragma unroll
    for (int o = 16; o > 0; o >>= 1) v += __shfl_xor_sync(0xffffffffu, v, o);
    return v;
}
__device__ __forceinline__ float warpMax(float v) {
#pragma unroll
    for (int o = 16; o > 0; o >>= 1) v = fmaxf(v, __shfl_xor_sync(0xffffffffu, v, o));
    return v;
}

__device__ __forceinline__ void ln_store(float4 v, const float* __restrict__ g,
                                         const float* __restrict__ b,
                                         float* __restrict__ outrow,
                                         __half* __restrict__ outrow16, int t) {
    __shared__ float red[8];
    __shared__ float stat[2];
    float s = v.x + v.y + v.z + v.w;
    s = warpSum(s);
    if ((t & 31) == 0) red[t >> 5] = s;
    __syncthreads();
    if (t < 32) {
        float x = (t < 8) ? red[t] : 0.0f;
        x = warpSum(x);
        if (t == 0) stat[0] = x * (1.0f / (float)HID);
    }
    __syncthreads();
    float m = stat[0];
    float dx = v.x - m, dy = v.y - m, dz = v.z - m, dw = v.w - m;
    float s2 = dx * dx + dy * dy + dz * dz + dw * dw;
    s2 = warpSum(s2);
    if ((t & 31) == 0) red[t >> 5] = s2;
    __syncthreads();
    if (t < 32) {
        float x = (t < 8) ? red[t] : 0.0f;
        x = warpSum(x);
        if (t == 0) stat[1] = rsqrtf(x * (1.0f / (float)HID) + 1e-7f);
    }
    __syncthreads();
    float r = stat[1];
    float4 gv = ((const float4*)g)[t];
    float4 bv = ((const float4*)b)[t];
    float4 o;
    o.x = dx * r * gv.x + bv.x;
    o.y = dy * r * gv.y + bv.y;
    o.z = dz * r * gv.z + bv.z;
    o.w = dw * r * gv.w + bv.w;
    if (outrow) ((float4*)outrow)[t] = o;
    if (outrow16) {
        __half2 h0 = __floats2half2_rn(o.x, o.y);
        __half2 h1 = __floats2half2_rn(o.z, o.w);
        uint2 u;
        u.x = *(uint32_t*)&h0; u.y = *(uint32_t*)&h1;
        ((uint2*)outrow16)[t] = u;
    }
}

__global__ void __launch_bounds__(256) k_embed(const float* __restrict__ x,
                                               const float* __restrict__ pos,
                                               const float* __restrict__ g,
                                               const float* __restrict__ b) {
    int row = blockIdx.x;
    int s = row & (SEQ - 1);
    int t = threadIdx.x;
    float4 xv = ((const float4*)(x + (size_t)row * HID))[t];
    float4 pv = ((const float4*)(pos + (size_t)s * HID))[t];
    xv.x += pv.x; xv.y += pv.y; xv.z += pv.z; xv.w += pv.w;
    ln_store(xv, g, b, g_h + (size_t)row * HID, g_h16 + (size_t)row * HID, t);
}

__global__ void __launch_bounds__(256) k_ln1(const float* __restrict__ g,
                                             const float* __restrict__ b) {
    int row = blockIdx.x;
    int t = threadIdx.x;
    float4 v = ((const float4*)(g_h + (size_t)row * HID))[t];
    ln_store(v, g, b, g_attn32 + (size_t)row * HID, g_attn16 + (size_t)row * HID, t);
}

__global__ void __launch_bounds__(256) k_ln2(const float* __restrict__ g,
                                             const float* __restrict__ b,
                                             float* __restrict__ out) {
    int row = blockIdx.x;
    int t = threadIdx.x;
    float4 v = ((const float4*)(g_h + (size_t)row * HID))[t];
    ln_store(v, g, b, out + (size_t)row * HID, (__half*)nullptr, t);
}

__global__ void __launch_bounds__(128) k_softmax() {
    __shared__ float red[4];
    __shared__ float stat0, stat1;
    size_t row = blockIdx.x;
    const float* p = g_s + row * SEQ;
    __half* po = g_p + row * SEQ;
    int t = threadIdx.x;
    float4 v = ((const float4*)p)[t];
    float mx = fmaxf(fmaxf(v.x, v.y), fmaxf(v.z, v.w));
    mx = warpMax(mx);
    if ((t & 31) == 0) red[t >> 5] = mx;
    __syncthreads();
    if (t < 32) {
        float x = (t < 4) ? red[t] : -3.4e38f;
        x = warpMax(x);
        if (t == 0) stat0 = x;
    }
    __syncthreads();
    mx = stat0;
    v.x = expf(v.x - mx); v.y = expf(v.y - mx);
    v.z = expf(v.z - mx); v.w = expf(v.w - mx);
    float s = v.x + v.y + v.z + v.w;
    s = warpSum(s);
    if ((t & 31) == 0) red[t >> 5] = s;
    __syncthreads();
    if (t < 32) {
        float x = (t < 4) ? red[t] : 0.0f;
        x = warpSum(x);
        if (t == 0) stat1 = 1.0f / x;
    }
    __syncthreads();
    float inv = stat1;
    __half2 h0 = __floats2half2_rn(v.x * inv, v.y * inv);
    __half2 h1 = __floats2half2_rn(v.z * inv, v.w * inv);
    uint2 u;
    u.x = *(uint32_t*)&h0; u.y = *(uint32_t*)&h1;
    ((uint2*)po)[t] = u;
}

// ---------------- launch ----------------
extern "C" void kernel_launch(void* const* d_in, const int* in_sizes, int n_in,
                              void* d_out, int out_size) {
    const float* x        = (const float*)d_in[0];
    const float* pos_emb  = (const float*)d_in[1];
    const float* emb_ln_g = (const float*)d_in[2];
    const float* emb_ln_b = (const float*)d_in[3];
    const float* Wq       = (const float*)d_in[4];
    const float* Wk       = (const float*)d_in[5];
    const float* Wv       = (const float*)d_in[6];
    const float* q_bias   = (const float*)d_in[7];
    const float* v_bias   = (const float*)d_in[8];
    const float* Wo       = (const float*)d_in[9];
    const float* bo       = (const float*)d_in[10];
    const float* ln1_g    = (const float*)d_in[11];
    const float* ln1_b    = (const float*)d_in[12];
    const float* Wi       = (const float*)d_in[13];
    const float* bi       = (const float*)d_in[14];
    const float* Wf       = (const float*)d_in[15];
    const float* bf       = (const float*)d_in[16];
    const float* ln2_g    = (const float*)d_in[17];
    const float* ln2_b    = (const float*)d_in[18];
    float* out = (float*)d_out;

    __half *wqt, *wkt, *wvt, *wot, *wit, *wft;
    cudaGetSymbolAddress((void**)&wqt, g_Wqt);
    cudaGetSymbolAddress((void**)&wkt, g_Wkt);
    cudaGetSymbolAddress((void**)&wvt, g_Wvt);
    cudaGetSymbolAddress((void**)&wot, g_Wot);
    cudaGetSymbolAddress((void**)&wit, g_Wit);
    cudaGetSymbolAddress((void**)&wft, g_Wft);

    // weight transposes (fp32 [K,N] -> fp16 [N,K])
    k_wt<<<dim3(HID / 32, HID / 32), 256>>>(Wq, wqt, HID, HID);
    k_wt<<<dim3(HID / 32, HID / 32), 256>>>(Wk, wkt, HID, HID);
    k_wt<<<dim3(HID / 32, HID / 32), 256>>>(Wv, wvt, HID, HID);
    k_wt<<<dim3(HID / 32, HID / 32), 256>>>(Wo, wot, HID, HID);
    k_wt<<<dim3(FFDIM / 32, HID / 32), 256>>>(Wi, wit, HID, FFDIM);
    k_wt<<<dim3(HID / 32, FFDIM / 32), 256>>>(Wf, wft, FFDIM, HID);

    dim3 gProj(HID / 128, MTOT / 128);                 // (8, 64)
    dim3 gFF1(FFDIM / 128, MTOT / 128);                // (24, 64)
    dim3 gScores(SEQ / 128, SEQ / 128, NBH);           // (4, 4, 128)
    dim3 gCtx(1, SEQ / 128, NBH);                      // (1, 4, 128)

    k_embed<<<MTOT, 256>>>(x, pos_emb, emb_ln_g, emb_ln_b);
    k_proj_q<<<gProj, 256>>>(q_bias);
    k_proj_k<<<gProj, 256>>>();
    k_proj_v<<<gProj, 256>>>(v_bias);
    k_vtrans<<<dim3(SEQ / 32, HDIM / 32, NBH), 256>>>();
    k_scores<<<gScores, 256>>>();
    k_softmax<<<NBH * SEQ, 128>>>();
    k_ctx<<<gCtx, 256>>>();
    k_proj_o<<<gProj, 256>>>(bo);
    k_ln1<<<MTOT, 256>>>(ln1_g, ln1_b);
    k_ff1<<<gFF1, 256>>>(bi);
    k_ff2<<<gProj, 256>>>(bf);
    k_ln2<<<MTOT, 256>>>(ln2_g, ln2_b, out);
}